// round 4
// baseline (speedup 1.0000x reference)
#include <cuda_runtime.h>
#include <cuda_fp16.h>
#include <cuda_bf16.h>

#define NUM_U 200000
#define NUM_I 100000
#define DIM   64
#define KTYP  4
#define E_A   1000000   // u2u
#define E_B   3200000   // u2i folds merged (item -> user agg)
#define E_C   1000000   // i2i
#define E_D   3200000   // i2u folds merged (user -> item agg)

// ---- scratch (device globals; no allocation allowed) ----
__device__ __half2 g_ueh[(size_t)KTYP * NUM_U * (DIM / 2)];
__device__ __half2 g_ieh[(size_t)KTYP * NUM_I * (DIM / 2)];
__device__ __half2 g_ub1h[(size_t)NUM_U * (DIM / 2)];
__device__ __half2 g_ib1h[(size_t)NUM_I * (DIM / 2)];

__device__ float2 g_packA[E_A];
__device__ float2 g_packB[E_B];
__device__ float2 g_packC[E_C];
__device__ float2 g_packD[E_D];

__device__ int g_offA[NUM_U + 1];
__device__ int g_offB[NUM_U + 1];
__device__ int g_offC[NUM_I + 1];
__device__ int g_offD[NUM_I + 1];
__device__ int g_curA[NUM_U];
__device__ int g_curB[NUM_U];
__device__ int g_curC[NUM_I];
__device__ int g_curD[NUM_I];
__device__ int g_bsums[256];

// ---------------------------------------------------------------------------
// fp32 -> half2 conversion
// ---------------------------------------------------------------------------
__global__ void convert_kernel(const float2* __restrict__ src,
                               __half2* __restrict__ dst, long long npairs)
{
    long long i = (long long)blockIdx.x * blockDim.x + threadIdx.x;
    if (i < npairs) {
        float2 f = __ldg(src + i);
        dst[i] = __floats2half2_rn(f.x, f.y);
    }
}

// ---------------------------------------------------------------------------
// CSR build: histogram -> 3-phase exclusive scan -> scatter
// ---------------------------------------------------------------------------
__global__ void hist_kernel(const int* __restrict__ rows, int nE,
                            int* __restrict__ counts, int roff)
{
    int i = blockIdx.x * blockDim.x + threadIdx.x;
    if (i < nE) atomicAdd(&counts[rows[i] + roff], 1);
}

__global__ void scan_phase1(const int* __restrict__ counts, int n,
                            int* __restrict__ bsums)
{
    __shared__ int sh[1024];
    int i = blockIdx.x * 1024 + threadIdx.x;
    sh[threadIdx.x] = (i < n) ? counts[i] : 0;
    __syncthreads();
    for (int s = 512; s > 0; s >>= 1) {
        if (threadIdx.x < s) sh[threadIdx.x] += sh[threadIdx.x + s];
        __syncthreads();
    }
    if (threadIdx.x == 0) bsums[blockIdx.x] = sh[0];
}

__global__ void scan_phase2(int* __restrict__ bsums, int nb,
                            int* __restrict__ off, int n)
{
    __shared__ int sh[256];
    int v = (threadIdx.x < nb) ? bsums[threadIdx.x] : 0;
    sh[threadIdx.x] = v;
    __syncthreads();
    for (int d = 1; d < 256; d <<= 1) {
        int t = (threadIdx.x >= d) ? sh[threadIdx.x - d] : 0;
        __syncthreads();
        sh[threadIdx.x] += t;
        __syncthreads();
    }
    if (threadIdx.x < nb) bsums[threadIdx.x] = sh[threadIdx.x] - v;
    if (threadIdx.x == 255) off[n] = sh[255];
}

__global__ void scan_phase3(const int* __restrict__ counts, int n,
                            const int* __restrict__ bsums, int* __restrict__ off)
{
    __shared__ int sh[1024];
    int i = blockIdx.x * 1024 + threadIdx.x;
    int v = (i < n) ? counts[i] : 0;
    sh[threadIdx.x] = v;
    __syncthreads();
    for (int d = 1; d < 1024; d <<= 1) {
        int t = (threadIdx.x >= d) ? sh[threadIdx.x - d] : 0;
        __syncthreads();
        sh[threadIdx.x] += t;
        __syncthreads();
    }
    if (i < n) off[i] = sh[threadIdx.x] - v + bsums[blockIdx.x];
}

__global__ void scatter_kernel(const int* __restrict__ rows,
                               const int* __restrict__ cols,
                               const float* __restrict__ vals, int nE,
                               int* __restrict__ cur, float2* __restrict__ pack,
                               int roff)
{
    int i = blockIdx.x * blockDim.x + threadIdx.x;
    if (i < nE) {
        int r = rows[i] + roff;
        int pos = atomicAdd(&cur[r], 1);
        pack[pos] = make_float2(__int_as_float(cols[i]), vals[i]);
    }
}

// ---------------------------------------------------------------------------
// 4x-unrolled CSR segment accumulate: MLP=4 on the gather path.
// ---------------------------------------------------------------------------
__device__ __forceinline__ void seg_accum(const float2* __restrict__ pack,
                                          const __half2* __restrict__ src,
                                          int s, int e, int lane,
                                          float& ax, float& ay)
{
    int i = s;
    for (; i + 4 <= e; i += 4) {
        float2 p0 = __ldcs(pack + i);
        float2 p1 = __ldcs(pack + i + 1);
        float2 p2 = __ldcs(pack + i + 2);
        float2 p3 = __ldcs(pack + i + 3);
        __half2 h0 = __ldg(src + (size_t)__float_as_int(p0.x) * 32 + lane);
        __half2 h1 = __ldg(src + (size_t)__float_as_int(p1.x) * 32 + lane);
        __half2 h2 = __ldg(src + (size_t)__float_as_int(p2.x) * 32 + lane);
        __half2 h3 = __ldg(src + (size_t)__float_as_int(p3.x) * 32 + lane);
        float2 v0 = __half22float2(h0);
        float2 v1 = __half22float2(h1);
        float2 v2 = __half22float2(h2);
        float2 v3 = __half22float2(h3);
        ax = fmaf(p0.y, v0.x, ax);  ay = fmaf(p0.y, v0.y, ay);
        ax = fmaf(p1.y, v1.x, ax);  ay = fmaf(p1.y, v1.y, ay);
        ax = fmaf(p2.y, v2.x, ax);  ay = fmaf(p2.y, v2.y, ay);
        ax = fmaf(p3.y, v3.x, ax);  ay = fmaf(p3.y, v3.y, ay);
    }
    for (; i < e; i++) {
        float2 p = __ldcs(pack + i);
        float2 v = __half22float2(__ldg(src + (size_t)__float_as_int(p.x) * 32 + lane));
        ax = fmaf(p.y, v.x, ax);
        ay = fmaf(p.y, v.y, ay);
    }
}

// ---------------------------------------------------------------------------
// Layer-1 dual-source CSR SpMM (half gather, fp32 accumulate, half store)
// ---------------------------------------------------------------------------
__global__ void __launch_bounds__(256) spmm_dual_h(
    const int* __restrict__ offA, const float2* __restrict__ packA,
    const __half2* __restrict__ srcA,
    const int* __restrict__ offB, const float2* __restrict__ packB,
    const __half2* __restrict__ srcB,
    __half2* __restrict__ dst, int nrows)
{
    int w = (blockIdx.x * blockDim.x + threadIdx.x) >> 5;
    int lane = threadIdx.x & 31;
    if (w >= nrows) return;

    float ax = 0.0f, ay = 0.0f;
    seg_accum(packA, srcA, __ldg(offA + w), __ldg(offA + w + 1), lane, ax, ay);
    seg_accum(packB, srcB, __ldg(offB + w), __ldg(offB + w + 1), lane, ax, ay);
    dst[(size_t)w * 32 + lane] = __floats2half2_rn(ax, ay);
}

// ---------------------------------------------------------------------------
// Fused layer-2 SpMM + layer-mean + 64x64 GEMM + ReLU -> fp32 output slice
// ---------------------------------------------------------------------------
__global__ void __launch_bounds__(256) spmm_fused(
    const int* __restrict__ offA, const float2* __restrict__ packA,
    const __half2* __restrict__ srcA,
    const int* __restrict__ offB, const float2* __restrict__ packB,
    const __half2* __restrict__ srcB,
    const float* __restrict__ e0,    // fp32 layer-0 [nrows*64]
    const __half2* __restrict__ e1,  // half layer-1 [nrows*32]
    const float* __restrict__ W,     // [64,64]
    float* __restrict__ out, int nrows, int out_stride, int out_off)
{
    __shared__ float Ws[DIM][DIM];
    for (int i = threadIdx.x; i < DIM * DIM; i += blockDim.x)
        Ws[i >> 6][i & 63] = W[i];
    __syncthreads();

    int w = (blockIdx.x * blockDim.x + threadIdx.x) >> 5;
    int lane = threadIdx.x & 31;
    if (w >= nrows) return;

    float ax = 0.0f, ay = 0.0f;
    seg_accum(packA, srcA, __ldg(offA + w), __ldg(offA + w + 1), lane, ax, ay);
    seg_accum(packB, srcB, __ldg(offB + w), __ldg(offB + w + 1), lane, ax, ay);

    const float inv3 = 1.0f / 3.0f;
    float2 f0 = __ldg(reinterpret_cast<const float2*>(e0 + (size_t)w * DIM) + lane);
    float2 f1 = __half22float2(__ldg(e1 + (size_t)w * 32 + lane));
    float m0 = (f0.x + f1.x + ax) * inv3;
    float m1 = (f0.y + f1.y + ay) * inv3;

    float acc0 = 0.0f, acc1 = 0.0f;
#pragma unroll
    for (int l = 0; l < 32; l++) {
        float b0 = __shfl_sync(0xffffffffu, m0, l);
        float b1 = __shfl_sync(0xffffffffu, m1, l);
        acc0 += b0 * Ws[2 * l][lane]      + b1 * Ws[2 * l + 1][lane];
        acc1 += b0 * Ws[2 * l][lane + 32] + b1 * Ws[2 * l + 1][lane + 32];
    }

    float* o = out + (size_t)w * out_stride + out_off;
    o[lane]      = fmaxf(acc0, 0.0f);
    o[lane + 32] = fmaxf(acc1, 0.0f);
}

// ---------------------------------------------------------------------------
// Host helpers
// ---------------------------------------------------------------------------
static void build_csr(const void* rows0, const void* cols0, const void* vals0, int n0, int roff0,
                      const void* rows1, const void* cols1, const void* vals1, int n1, int roff1,
                      int* cur, int* off, float2* pack, int nrows, int* bsums)
{
    cudaMemsetAsync(cur, 0, (size_t)nrows * sizeof(int), 0);
    hist_kernel<<<(n0 + 255) / 256, 256>>>((const int*)rows0, n0, cur, roff0);
    if (rows1)
        hist_kernel<<<(n1 + 255) / 256, 256>>>((const int*)rows1, n1, cur, roff1);

    int nb = (nrows + 1023) / 1024;
    scan_phase1<<<nb, 1024>>>(cur, nrows, bsums);
    scan_phase2<<<1, 256>>>(bsums, nb, off, nrows);
    scan_phase3<<<nb, 1024>>>(cur, nrows, bsums, off);

    cudaMemcpyAsync(cur, off, (size_t)nrows * sizeof(int),
                    cudaMemcpyDeviceToDevice, 0);

    scatter_kernel<<<(n0 + 255) / 256, 256>>>((const int*)rows0, (const int*)cols0,
                                              (const float*)vals0, n0, cur, pack, roff0);
    if (rows1)
        scatter_kernel<<<(n1 + 255) / 256, 256>>>((const int*)rows1, (const int*)cols1,
                                                  (const float*)vals1, n1, cur, pack, roff1);
}

extern "C" void kernel_launch(void* const* d_in, const int* in_sizes, int n_in,
                              void* d_out, int out_size)
{
    const void* u2u_r  = d_in[0];  const void* u2u_c  = d_in[1];  const void* u2u_v  = d_in[2];
    const void* u2i_r0 = d_in[3];  const void* u2i_c0 = d_in[4];  const void* u2i_v0 = d_in[5];
    const void* u2i_r1 = d_in[6];  const void* u2i_c1 = d_in[7];  const void* u2i_v1 = d_in[8];
    const void* i2u_r0 = d_in[9];  const void* i2u_c0 = d_in[10]; const void* i2u_v0 = d_in[11];
    const void* i2u_r1 = d_in[12]; const void* i2u_c1 = d_in[13]; const void* i2u_v1 = d_in[14];
    const void* i2i_r  = d_in[15]; const void* i2i_c  = d_in[16]; const void* i2i_v  = d_in[17];
    const float* user_embs = (const float*)d_in[18];
    const float* item_embs = (const float*)d_in[19];
    const float* W_u       = (const float*)d_in[20];
    const float* W_v       = (const float*)d_in[21];

    const int E_uu  = in_sizes[0];
    const int E_ui0 = in_sizes[3], E_ui1 = in_sizes[6];
    const int E_iu0 = in_sizes[9], E_iu1 = in_sizes[12];
    const int E_ii  = in_sizes[15];

    float* out_user = (float*)d_out;
    float* out_item = (float*)d_out + (size_t)NUM_U * (KTYP * DIM);

    __half2 *ueh, *ieh, *ub1h, *ib1h;
    float2 *pA, *pB, *pC, *pD;
    int *oA, *oB, *oC, *oD, *cA, *cB, *cC, *cD, *bs;
    cudaGetSymbolAddress((void**)&ueh, g_ueh);
    cudaGetSymbolAddress((void**)&ieh, g_ieh);
    cudaGetSymbolAddress((void**)&ub1h, g_ub1h);
    cudaGetSymbolAddress((void**)&ib1h, g_ib1h);
    cudaGetSymbolAddress((void**)&pA, g_packA);
    cudaGetSymbolAddress((void**)&pB, g_packB);
    cudaGetSymbolAddress((void**)&pC, g_packC);
    cudaGetSymbolAddress((void**)&pD, g_packD);
    cudaGetSymbolAddress((void**)&oA, g_offA);
    cudaGetSymbolAddress((void**)&oB, g_offB);
    cudaGetSymbolAddress((void**)&oC, g_offC);
    cudaGetSymbolAddress((void**)&oD, g_offD);
    cudaGetSymbolAddress((void**)&cA, g_curA);
    cudaGetSymbolAddress((void**)&cB, g_curB);
    cudaGetSymbolAddress((void**)&cC, g_curC);
    cudaGetSymbolAddress((void**)&cD, g_curD);
    cudaGetSymbolAddress((void**)&bs, g_bsums);

    {
        long long up = (long long)KTYP * NUM_U * 32;
        long long ip = (long long)KTYP * NUM_I * 32;
        convert_kernel<<<(int)((up + 255) / 256), 256>>>((const float2*)user_embs, ueh, up);
        convert_kernel<<<(int)((ip + 255) / 256), 256>>>((const float2*)item_embs, ieh, ip);
    }

    build_csr(u2u_r, u2u_c, u2u_v, E_uu, 0,
              nullptr, nullptr, nullptr, 0, 0, cA, oA, pA, NUM_U, bs);
    build_csr(u2i_r0, u2i_c0, u2i_v0, E_ui0, 0,
              u2i_r1, u2i_c1, u2i_v1, E_ui1, NUM_U / 2, cB, oB, pB, NUM_U, bs);
    build_csr(i2i_r, i2i_c, i2i_v, E_ii, 0,
              nullptr, nullptr, nullptr, 0, 0, cC, oC, pC, NUM_I, bs);
    build_csr(i2u_r0, i2u_c0, i2u_v0, E_iu0, 0,
              i2u_r1, i2u_c1, i2u_v1, E_iu1, NUM_I / 2, cD, oD, pD, NUM_I, bs);

    const int TPB = 256;
    const int gu = (NUM_U + 7) / 8;
    const int gi = (NUM_I + 7) / 8;

    for (int k = 0; k < KTYP; k++) {
        const float*   ue0f = user_embs + (size_t)k * NUM_U * DIM;
        const float*   ie0f = item_embs + (size_t)k * NUM_I * DIM;
        const __half2* ue0h = ueh + (size_t)k * NUM_U * 32;
        const __half2* ie0h = ieh + (size_t)k * NUM_I * 32;

        spmm_dual_h<<<gu, TPB>>>(oA, pA, ue0h, oB, pB, ie0h, ub1h, NUM_U);
        spmm_dual_h<<<gi, TPB>>>(oC, pC, ie0h, oD, pD, ue0h, ib1h, NUM_I);

        spmm_fused<<<gu, TPB>>>(oA, pA, ub1h, oB, pB, ib1h,
                                ue0f, ub1h, W_u + (size_t)k * DIM * DIM,
                                out_user, NUM_U, KTYP * DIM, k * DIM);
        spmm_fused<<<gi, TPB>>>(oC, pC, ib1h, oD, pD, ub1h,
                                ie0f, ib1h, W_v + (size_t)k * DIM * DIM,
                                out_item, NUM_I, KTYP * DIM, k * DIM);
    }
}

// round 5
// speedup vs baseline: 1.0949x; 1.0949x over previous
#include <cuda_runtime.h>
#include <cuda_fp16.h>
#include <cuda_bf16.h>

#define NUM_U 200000
#define NUM_I 100000
#define DIM   64
#define KTYP  4
#define E_A   1000000   // u2u
#define E_B   3200000   // u2i folds merged (item -> user agg), CSR by user row
#define E_C   1000000   // i2i, CSC by item col
#define E_D   3200000   // i2u folds merged (user -> item agg), CSC by user col

// ---- scratch (device globals) ----
__device__ __half2 g_ueh[(size_t)KTYP * NUM_U * 32];
__device__ __half2 g_ieh[(size_t)KTYP * NUM_I * 32];
__device__ __half2 g_ub1h[(size_t)NUM_U * 32];
__device__ __half2 g_ib1h[(size_t)NUM_I * 32];
__device__ __half2 g_ib2h[(size_t)NUM_I * 32];

__device__ float2 g_packA[E_A];
__device__ float2 g_packB[E_B];
__device__ float2 g_packC[E_C];
__device__ float2 g_packD[E_D];

__device__ int g_offA[NUM_U + 1];
__device__ int g_offB[NUM_U + 1];
__device__ int g_offC[NUM_I + 1];
__device__ int g_offD[NUM_U + 1];
__device__ int g_curA[NUM_U];
__device__ int g_curB[NUM_U];
__device__ int g_curC[NUM_I];
__device__ int g_curD[NUM_U];
__device__ int g_bsums[256];

// ---------------------------------------------------------------------------
// fp32 -> half2 conversion
// ---------------------------------------------------------------------------
__global__ void convert_kernel(const float2* __restrict__ src,
                               __half2* __restrict__ dst, long long npairs)
{
    long long i = (long long)blockIdx.x * blockDim.x + threadIdx.x;
    if (i < npairs) {
        float2 f = __ldg(src + i);
        dst[i] = __floats2half2_rn(f.x, f.y);
    }
}

// ---------------------------------------------------------------------------
// CSR/CSC build: histogram -> 3-phase exclusive scan -> scatter
// ---------------------------------------------------------------------------
__global__ void hist_kernel(const int* __restrict__ keys, int nE,
                            int* __restrict__ counts, int koff)
{
    int i = blockIdx.x * blockDim.x + threadIdx.x;
    if (i < nE) atomicAdd(&counts[keys[i] + koff], 1);
}

__global__ void scan_phase1(const int* __restrict__ counts, int n,
                            int* __restrict__ bsums)
{
    __shared__ int sh[1024];
    int i = blockIdx.x * 1024 + threadIdx.x;
    sh[threadIdx.x] = (i < n) ? counts[i] : 0;
    __syncthreads();
    for (int s = 512; s > 0; s >>= 1) {
        if (threadIdx.x < s) sh[threadIdx.x] += sh[threadIdx.x + s];
        __syncthreads();
    }
    if (threadIdx.x == 0) bsums[blockIdx.x] = sh[0];
}

__global__ void scan_phase2(int* __restrict__ bsums, int nb,
                            int* __restrict__ off, int n)
{
    __shared__ int sh[256];
    int v = (threadIdx.x < nb) ? bsums[threadIdx.x] : 0;
    sh[threadIdx.x] = v;
    __syncthreads();
    for (int d = 1; d < 256; d <<= 1) {
        int t = (threadIdx.x >= d) ? sh[threadIdx.x - d] : 0;
        __syncthreads();
        sh[threadIdx.x] += t;
        __syncthreads();
    }
    if (threadIdx.x < nb) bsums[threadIdx.x] = sh[threadIdx.x] - v;
    if (threadIdx.x == 255) off[n] = sh[255];
}

__global__ void scan_phase3(const int* __restrict__ counts, int n,
                            const int* __restrict__ bsums, int* __restrict__ off)
{
    __shared__ int sh[1024];
    int i = blockIdx.x * 1024 + threadIdx.x;
    int v = (i < n) ? counts[i] : 0;
    sh[threadIdx.x] = v;
    __syncthreads();
    for (int d = 1; d < 1024; d <<= 1) {
        int t = (threadIdx.x >= d) ? sh[threadIdx.x - d] : 0;
        __syncthreads();
        sh[threadIdx.x] += t;
        __syncthreads();
    }
    if (i < n) off[i] = sh[threadIdx.x] - v + bsums[blockIdx.x];
}

// CSR scatter: key = row (+roff), payload = (col, val)
__global__ void scatter_csr(const int* __restrict__ rows,
                            const int* __restrict__ cols,
                            const float* __restrict__ vals, int nE,
                            int* __restrict__ cur, float2* __restrict__ pack,
                            int roff)
{
    int i = blockIdx.x * blockDim.x + threadIdx.x;
    if (i < nE) {
        int pos = atomicAdd(&cur[rows[i] + roff], 1);
        pack[pos] = make_float2(__int_as_float(cols[i]), vals[i]);
    }
}

// CSC scatter: key = col, payload = (dst_row + dstoff, val)
__global__ void scatter_csc(const int* __restrict__ rows,
                            const int* __restrict__ cols,
                            const float* __restrict__ vals, int nE,
                            int* __restrict__ cur, float2* __restrict__ pack,
                            int dstoff)
{
    int i = blockIdx.x * blockDim.x + threadIdx.x;
    if (i < nE) {
        int pos = atomicAdd(&cur[cols[i]], 1);
        pack[pos] = make_float2(__int_as_float(rows[i] + dstoff), vals[i]);
    }
}

// ---------------------------------------------------------------------------
// Gather segment accumulate (plain loop; proven 4.2 TB/s read-path)
// ---------------------------------------------------------------------------
__device__ __forceinline__ void seg_accum(const float2* __restrict__ pack,
                                          const __half2* __restrict__ src,
                                          int s, int e, int lane,
                                          float& ax, float& ay)
{
    for (int i = s; i < e; i++) {
        float2 p = __ldg(pack + i);
        float2 v = __half22float2(__ldg(src + (size_t)__float_as_int(p.x) * 32 + lane));
        ax = fmaf(p.y, v.x, ax);
        ay = fmaf(p.y, v.y, ay);
    }
}

// ---------------------------------------------------------------------------
// Scatter one source column: dst[row,:] += val * src[col,:] via v4.f16x2 reds.
// Warp handles 4 edges/iter: 8 lanes per edge, 16B red per lane.
// ---------------------------------------------------------------------------
__device__ __forceinline__ unsigned pk_h2(__half2 h, float v)
{
    float2 f = __half22float2(h);
    __half2 r = __floats2half2_rn(v * f.x, v * f.y);
    return *reinterpret_cast<unsigned*>(&r);
}

__device__ __forceinline__ void scatter_col(const int* __restrict__ off,
                                            const float2* __restrict__ pack,
                                            const __half2* __restrict__ src,
                                            __half2* __restrict__ dstbase,
                                            int col, int lane)
{
    int s = __ldg(off + col), e = __ldg(off + col + 1);
    if (s == e) return;
    __half2 rl = __ldg(src + (size_t)col * 32 + lane);
    int j  = lane & 7;    // 16B chunk within row
    int ei = lane >> 3;   // edge slot 0..3
    __half2 r0 = __shfl_sync(0xffffffffu, rl, 4 * j + 0);
    __half2 r1 = __shfl_sync(0xffffffffu, rl, 4 * j + 1);
    __half2 r2 = __shfl_sync(0xffffffffu, rl, 4 * j + 2);
    __half2 r3 = __shfl_sync(0xffffffffu, rl, 4 * j + 3);
    for (int base = s; base < e; base += 4) {
        int i = base + ei;
        if (i < e) {
            float2 p = __ldg(pack + i);
            int dst = __float_as_int(p.x);
            float v = p.y;
            unsigned q0 = pk_h2(r0, v), q1 = pk_h2(r1, v);
            unsigned q2 = pk_h2(r2, v), q3 = pk_h2(r3, v);
            __half2* ptr = dstbase + (size_t)dst * 32 + 4 * j;
            asm volatile("red.global.add.noftz.v4.f16x2 [%0], {%1,%2,%3,%4};"
                         :: "l"(ptr), "r"(q0), "r"(q1), "r"(q2), "r"(q3)
                         : "memory");
        }
    }
}

// ---------------------------------------------------------------------------
// Layer 1 combined: user-side gather (CSR) + item-side scatter (CSC),
// roles interleaved across blocks so both L2 paths stay busy.
// ---------------------------------------------------------------------------
#define GU1 25000
#define GS1 37500
#define T1  (GU1 + GS1)

__global__ void __launch_bounds__(256) combined_l1(
    const int* __restrict__ offA, const float2* __restrict__ packA,
    const int* __restrict__ offB, const float2* __restrict__ packB,
    const int* __restrict__ offC, const float2* __restrict__ packC,
    const int* __restrict__ offD, const float2* __restrict__ packD,
    const __half2* __restrict__ ueh_k, const __half2* __restrict__ ieh_k,
    __half2* __restrict__ ub1, __half2* __restrict__ ib1)
{
    int t = blockIdx.x;
    int warp = threadIdx.x >> 5, lane = threadIdx.x & 31;
    long long lo = (long long)t * GU1 / T1;
    long long hi = (long long)(t + 1) * GU1 / T1;
    if (hi > lo) {
        // gather role: user row
        int w = (int)lo * 8 + warp;
        float ax = 0.0f, ay = 0.0f;
        seg_accum(packA, ueh_k, __ldg(offA + w), __ldg(offA + w + 1), lane, ax, ay);
        seg_accum(packB, ieh_k, __ldg(offB + w), __ldg(offB + w + 1), lane, ax, ay);
        ub1[(size_t)w * 32 + lane] = __floats2half2_rn(ax, ay);
    } else {
        // scatter role: item destinations
        int wg = (t - (int)hi) * 8 + warp;
        if (wg < NUM_I)
            scatter_col(offC, packC, ieh_k, ib1, wg, lane);
        else
            scatter_col(offD, packD, ueh_k, ib1, wg - NUM_I, lane);
    }
}

// ---------------------------------------------------------------------------
// Layer 2 combined: user gather fused with mean+GEMM+ReLU, item scatter -> ib2
// ---------------------------------------------------------------------------
#define GU2 6250          // each gather block loops 4 row-groups (Ws amortized)
#define T2  (GU2 + GS1)

__global__ void __launch_bounds__(256) combined_l2(
    const int* __restrict__ offA, const float2* __restrict__ packA,
    const int* __restrict__ offB, const float2* __restrict__ packB,
    const int* __restrict__ offC, const float2* __restrict__ packC,
    const int* __restrict__ offD, const float2* __restrict__ packD,
    const __half2* __restrict__ ub1, const __half2* __restrict__ ib1,
    __half2* __restrict__ ib2,
    const float* __restrict__ ue0f,       // fp32 layer-0 user
    const float* __restrict__ W,          // [64,64]
    float* __restrict__ out, int out_stride, int out_off)
{
    __shared__ float Ws[DIM][DIM];
    int t = blockIdx.x;
    int warp = threadIdx.x >> 5, lane = threadIdx.x & 31;
    long long lo = (long long)t * GU2 / T2;
    long long hi = (long long)(t + 1) * GU2 / T2;
    if (hi > lo) {
        for (int i = threadIdx.x; i < DIM * DIM; i += blockDim.x)
            Ws[i >> 6][i & 63] = W[i];
        __syncthreads();

        for (int w = (int)lo * 8 + warp; w < NUM_U; w += GU2 * 8) {
            float ax = 0.0f, ay = 0.0f;
            seg_accum(packA, ub1, __ldg(offA + w), __ldg(offA + w + 1), lane, ax, ay);
            seg_accum(packB, ib1, __ldg(offB + w), __ldg(offB + w + 1), lane, ax, ay);

            const float inv3 = 1.0f / 3.0f;
            float2 f0 = __ldg(reinterpret_cast<const float2*>(ue0f + (size_t)w * DIM) + lane);
            float2 f1 = __half22float2(__ldg(ub1 + (size_t)w * 32 + lane));
            float m0 = (f0.x + f1.x + ax) * inv3;
            float m1 = (f0.y + f1.y + ay) * inv3;

            float acc0 = 0.0f, acc1 = 0.0f;
#pragma unroll
            for (int l = 0; l < 32; l++) {
                float b0 = __shfl_sync(0xffffffffu, m0, l);
                float b1 = __shfl_sync(0xffffffffu, m1, l);
                acc0 += b0 * Ws[2 * l][lane]      + b1 * Ws[2 * l + 1][lane];
                acc1 += b0 * Ws[2 * l][lane + 32] + b1 * Ws[2 * l + 1][lane + 32];
            }
            float* o = out + (size_t)w * out_stride + out_off;
            o[lane]      = fmaxf(acc0, 0.0f);
            o[lane + 32] = fmaxf(acc1, 0.0f);
        }
    } else {
        int wg = (t - (int)hi) * 8 + warp;
        if (wg < NUM_I)
            scatter_col(offC, packC, ib1, ib2, wg, lane);
        else
            scatter_col(offD, packD, ub1, ib2, wg - NUM_I, lane);
    }
}

// ---------------------------------------------------------------------------
// Item combine: mean(ie0, ib1, ib2) @ W_v, ReLU -> output slice
// ---------------------------------------------------------------------------
__global__ void __launch_bounds__(256) item_combine(
    const float* __restrict__ ie0f,
    const __half2* __restrict__ ib1, const __half2* __restrict__ ib2,
    const float* __restrict__ W, float* __restrict__ out,
    int out_stride, int out_off)
{
    __shared__ float Ws[DIM][DIM];
    for (int i = threadIdx.x; i < DIM * DIM; i += blockDim.x)
        Ws[i >> 6][i & 63] = W[i];
    __syncthreads();

    int warp = threadIdx.x >> 5, lane = threadIdx.x & 31;
    for (int w = blockIdx.x * 8 + warp; w < NUM_I; w += gridDim.x * 8) {
        const float inv3 = 1.0f / 3.0f;
        float2 f0 = __ldg(reinterpret_cast<const float2*>(ie0f + (size_t)w * DIM) + lane);
        float2 f1 = __half22float2(__ldg(ib1 + (size_t)w * 32 + lane));
        float2 f2 = __half22float2(__ldg(ib2 + (size_t)w * 32 + lane));
        float m0 = (f0.x + f1.x + f2.x) * inv3;
        float m1 = (f0.y + f1.y + f2.y) * inv3;

        float acc0 = 0.0f, acc1 = 0.0f;
#pragma unroll
        for (int l = 0; l < 32; l++) {
            float b0 = __shfl_sync(0xffffffffu, m0, l);
            float b1 = __shfl_sync(0xffffffffu, m1, l);
            acc0 += b0 * Ws[2 * l][lane]      + b1 * Ws[2 * l + 1][lane];
            acc1 += b0 * Ws[2 * l][lane + 32] + b1 * Ws[2 * l + 1][lane + 32];
        }
        float* o = out + (size_t)w * out_stride + out_off;
        o[lane]      = fmaxf(acc0, 0.0f);
        o[lane + 32] = fmaxf(acc1, 0.0f);
    }
}

// ---------------------------------------------------------------------------
// Host-side structure builders
// ---------------------------------------------------------------------------
static void run_scans(int* cur, int* off, int n, int* bsums)
{
    int nb = (n + 1023) / 1024;
    scan_phase1<<<nb, 1024>>>(cur, n, bsums);
    scan_phase2<<<1, 256>>>(bsums, nb, off, n);
    scan_phase3<<<nb, 1024>>>(cur, n, bsums, off);
    cudaMemcpyAsync(cur, off, (size_t)n * sizeof(int), cudaMemcpyDeviceToDevice, 0);
}

extern "C" void kernel_launch(void* const* d_in, const int* in_sizes, int n_in,
                              void* d_out, int out_size)
{
    const int* u2u_r  = (const int*)d_in[0];  const int* u2u_c  = (const int*)d_in[1];
    const float* u2u_v = (const float*)d_in[2];
    const int* u2i_r0 = (const int*)d_in[3];  const int* u2i_c0 = (const int*)d_in[4];
    const float* u2i_v0 = (const float*)d_in[5];
    const int* u2i_r1 = (const int*)d_in[6];  const int* u2i_c1 = (const int*)d_in[7];
    const float* u2i_v1 = (const float*)d_in[8];
    const int* i2u_r0 = (const int*)d_in[9];  const int* i2u_c0 = (const int*)d_in[10];
    const float* i2u_v0 = (const float*)d_in[11];
    const int* i2u_r1 = (const int*)d_in[12]; const int* i2u_c1 = (const int*)d_in[13];
    const float* i2u_v1 = (const float*)d_in[14];
    const int* i2i_r  = (const int*)d_in[15]; const int* i2i_c  = (const int*)d_in[16];
    const float* i2i_v = (const float*)d_in[17];
    const float* user_embs = (const float*)d_in[18];
    const float* item_embs = (const float*)d_in[19];
    const float* W_u       = (const float*)d_in[20];
    const float* W_v       = (const float*)d_in[21];

    const int E_uu  = in_sizes[0];
    const int E_ui0 = in_sizes[3], E_ui1 = in_sizes[6];
    const int E_iu0 = in_sizes[9], E_iu1 = in_sizes[12];
    const int E_ii  = in_sizes[15];

    float* out_user = (float*)d_out;
    float* out_item = (float*)d_out + (size_t)NUM_U * (KTYP * DIM);

    __half2 *ueh, *ieh, *ub1, *ib1, *ib2;
    float2 *pA, *pB, *pC, *pD;
    int *oA, *oB, *oC, *oD, *cA, *cB, *cC, *cD, *bs;
    cudaGetSymbolAddress((void**)&ueh, g_ueh);
    cudaGetSymbolAddress((void**)&ieh, g_ieh);
    cudaGetSymbolAddress((void**)&ub1, g_ub1h);
    cudaGetSymbolAddress((void**)&ib1, g_ib1h);
    cudaGetSymbolAddress((void**)&ib2, g_ib2h);
    cudaGetSymbolAddress((void**)&pA, g_packA);
    cudaGetSymbolAddress((void**)&pB, g_packB);
    cudaGetSymbolAddress((void**)&pC, g_packC);
    cudaGetSymbolAddress((void**)&pD, g_packD);
    cudaGetSymbolAddress((void**)&oA, g_offA);
    cudaGetSymbolAddress((void**)&oB, g_offB);
    cudaGetSymbolAddress((void**)&oC, g_offC);
    cudaGetSymbolAddress((void**)&oD, g_offD);
    cudaGetSymbolAddress((void**)&cA, g_curA);
    cudaGetSymbolAddress((void**)&cB, g_curB);
    cudaGetSymbolAddress((void**)&cC, g_curC);
    cudaGetSymbolAddress((void**)&cD, g_curD);
    cudaGetSymbolAddress((void**)&bs, g_bsums);

    // ---- convert tables to half ----
    {
        long long up = (long long)KTYP * NUM_U * 32;
        long long ip = (long long)KTYP * NUM_I * 32;
        convert_kernel<<<(int)((up + 255) / 256), 256>>>((const float2*)user_embs, ueh, up);
        convert_kernel<<<(int)((ip + 255) / 256), 256>>>((const float2*)item_embs, ieh, ip);
    }

    // ---- A: u2u CSR (by user row) ----
    cudaMemsetAsync(cA, 0, NUM_U * sizeof(int), 0);
    hist_kernel<<<(E_uu + 255) / 256, 256>>>(u2u_r, E_uu, cA, 0);
    run_scans(cA, oA, NUM_U, bs);
    scatter_csr<<<(E_uu + 255) / 256, 256>>>(u2u_r, u2u_c, u2u_v, E_uu, cA, pA, 0);

    // ---- B: u2i folds CSR (by user row; fold1 rows offset NUM_U/2) ----
    cudaMemsetAsync(cB, 0, NUM_U * sizeof(int), 0);
    hist_kernel<<<(E_ui0 + 255) / 256, 256>>>(u2i_r0, E_ui0, cB, 0);
    hist_kernel<<<(E_ui1 + 255) / 256, 256>>>(u2i_r1, E_ui1, cB, NUM_U / 2);
    run_scans(cB, oB, NUM_U, bs);
    scatter_csr<<<(E_ui0 + 255) / 256, 256>>>(u2i_r0, u2i_c0, u2i_v0, E_ui0, cB, pB, 0);
    scatter_csr<<<(E_ui1 + 255) / 256, 256>>>(u2i_r1, u2i_c1, u2i_v1, E_ui1, cB, pB, NUM_U / 2);
    // NOTE: scatter_csr keys on rows[i]+roff: fold1 must key rows+NUM_U/2
    // (handled because scatter_csr uses rows[i]+roff for cur index)

    // ---- C: i2i CSC (by item source col; payload dst item row) ----
    cudaMemsetAsync(cC, 0, NUM_I * sizeof(int), 0);
    hist_kernel<<<(E_ii + 255) / 256, 256>>>(i2i_c, E_ii, cC, 0);
    run_scans(cC, oC, NUM_I, bs);
    scatter_csc<<<(E_ii + 255) / 256, 256>>>(i2i_r, i2i_c, i2i_v, E_ii, cC, pC, 0);

    // ---- D: i2u folds CSC (by user source col; dst item row, fold1 +NUM_I/2) ----
    cudaMemsetAsync(cD, 0, NUM_U * sizeof(int), 0);
    hist_kernel<<<(E_iu0 + 255) / 256, 256>>>(i2u_c0, E_iu0, cD, 0);
    hist_kernel<<<(E_iu1 + 255) / 256, 256>>>(i2u_c1, E_iu1, cD, 0);
    run_scans(cD, oD, NUM_U, bs);
    scatter_csc<<<(E_iu0 + 255) / 256, 256>>>(i2u_r0, i2u_c0, i2u_v0, E_iu0, cD, pD, 0);
    scatter_csc<<<(E_iu1 + 255) / 256, 256>>>(i2u_r1, i2u_c1, i2u_v1, E_iu1, cD, pD, NUM_I / 2);

    const size_t IB_BYTES = (size_t)NUM_I * 32 * sizeof(__half2);

    for (int k = 0; k < KTYP; k++) {
        const float*   ue0f = user_embs + (size_t)k * NUM_U * DIM;
        const float*   ie0f = item_embs + (size_t)k * NUM_I * DIM;
        const __half2* uk   = ueh + (size_t)k * NUM_U * 32;
        const __half2* ik   = ieh + (size_t)k * NUM_I * 32;

        cudaMemsetAsync(ib1, 0, IB_BYTES, 0);
        combined_l1<<<T1, 256>>>(oA, pA, oB, pB, oC, pC, oD, pD, uk, ik, ub1, ib1);

        cudaMemsetAsync(ib2, 0, IB_BYTES, 0);
        combined_l2<<<T2, 256>>>(oA, pA, oB, pB, oC, pC, oD, pD,
                                 ub1, ib1, ib2, ue0f,
                                 W_u + (size_t)k * DIM * DIM,
                                 out_user, KTYP * DIM, k * DIM);

        item_combine<<<3125, 256>>>(ie0f, ib1, ib2,
                                    W_v + (size_t)k * DIM * DIM,
                                    out_item, KTYP * DIM, k * DIM);
    }
}